// round 3
// baseline (speedup 1.0000x reference)
#include <cuda_runtime.h>
#include <cstdint>
#include <math.h>

#define DEV_INLINE __device__ __forceinline__

constexpr int B_   = 32;
constexpr int H_   = 32;
constexpr int HKV_ = 8;
constexpr int D_   = 128;
constexpr int G_   = 4;       // H_/HKV_
constexpr int N_   = 4096;
constexpr int NB_  = 256;     // 16-token blocks per sequence
constexpr int SPLIT = 8;      // token splits per (b,kh)
constexpr int WARPS = 8;
constexpr int TPS = N_ / SPLIT;        // 512 tokens per CTA
constexpr int STAGES_TOT = TPS / 16;   // 32 paged blocks per CTA
constexpr int DEPTH = 3;               // smem ring depth (3 x 16KB = 48KB static)
constexpr float SCALE_ = 0.08838834764831845f;

// Partial results scratch (allocation-free __device__ globals)
// layout: [b][kh][split][g] -> acc[128], (M,L)
__device__ float g_pacc[(size_t)B_ * HKV_ * SPLIT * G_ * D_];
__device__ float g_pml[(size_t)B_ * HKV_ * SPLIT * G_ * 2];

DEV_INLINE void cp_async16(unsigned int smem_addr, const void* gptr) {
    asm volatile("cp.async.cg.shared.global [%0], [%1], 16;\n"
                 :: "r"(smem_addr), "l"(gptr));
}
DEV_INLINE void cp_commit() { asm volatile("cp.async.commit_group;\n"); }
template <int NN> DEV_INLINE void cp_wait() {
    asm volatile("cp.async.wait_group %0;\n" :: "n"(NN));
}

// Stage layout (float4 units): [0,512) = K block (16 tok x 128 f), [512,1024) = V block
DEV_INLINE void issue_stage(float4* stbase, const float* gK, const float* gV, int tid) {
    unsigned int sK = (unsigned int)__cvta_generic_to_shared(stbase);
    #pragma unroll
    for (int r = 0; r < 2; r++) {
        const int c = tid + r * 256;           // chunk 0..511
        cp_async16(sK + c * 16,        gK + c * 4);
        cp_async16(sK + 8192 + c * 16, gV + c * 4);
    }
}

__global__ __launch_bounds__(256, 2)
void attn_main(const float* __restrict__ Q,
               const float* __restrict__ Kc,
               const float* __restrict__ Vc,
               const float* __restrict__ cosp,
               const float* __restrict__ sinp,
               const int* __restrict__ bt)
{
    const int b  = blockIdx.z;
    const int kh = blockIdx.y;
    const int sp = blockIdx.x;
    const int tid = threadIdx.x;
    const int w   = tid >> 5;
    const int lid = tid & 31;
    const int g   = lid >> 3;        // query-head group 0..3
    const int seg = lid & 7;         // d-segment 0..7
    const int d0  = seg * 16;
    const int h   = g * HKV_ + kh;

    __shared__ float4 ssm[DEPTH * 1024];   // 48 KB ring (aliased for combine at end)

    // RoPE'd + pre-scaled Q segment
    float qr[16];
    {
        const float* qb = Q + ((size_t)b * H_ + h) * D_;
        const float* cb = cosp + (size_t)b * D_;
        const float* sb = sinp + (size_t)b * D_;
        const float sign = (d0 < 64) ? -1.f : 1.f;
        const int dp = d0 ^ 64;
        #pragma unroll
        for (int k = 0; k < 16; k++)
            qr[k] = (qb[d0 + k] * cb[d0 + k] + sign * qb[dp + k] * sb[d0 + k]) * SCALE_;
    }

    const int* btb = bt + (size_t)b * NB_ + sp * STAGES_TOT;

    // pipeline prologue: issue DEPTH stages
    #pragma unroll
    for (int s = 0; s < DEPTH; s++) {
        const int blk = __ldg(btb + s);
        const size_t o = (size_t)blk * 16384 + (size_t)kh * 2048;
        issue_stage(ssm + s * 1024, Kc + o, Vc + o, tid);
        cp_commit();
    }

    float m = -1e30f, l = 0.f;
    float acc[16];
    #pragma unroll
    for (int k = 0; k < 16; k++) acc[k] = 0.f;

    for (int st = 0; st < STAGES_TOT; st++) {
        cp_wait<DEPTH - 1>();
        __syncthreads();

        float4* stb = ssm + (st % DEPTH) * 1024;
        const int tbase = sp * TPS + st * 16;
        const int jm = min(16, (N_ - 1) - tbase);   // exclude current token (combine handles it)

        #pragma unroll
        for (int tt = 0; tt < 2; tt++) {
            const int j = w + tt * 8;
            if (j < jm) {
                const float4* kp = stb + j * 32 + seg * 4;
                const float4* vp = kp + 512;
                float4 k0 = kp[0], k1 = kp[1], k2 = kp[2], k3 = kp[3];
                float4 v0 = vp[0], v1 = vp[1], v2 = vp[2], v3 = vp[3];

                float s = qr[0]*k0.x + qr[1]*k0.y + qr[2]*k0.z + qr[3]*k0.w
                        + qr[4]*k1.x + qr[5]*k1.y + qr[6]*k1.z + qr[7]*k1.w
                        + qr[8]*k2.x + qr[9]*k2.y + qr[10]*k2.z + qr[11]*k2.w
                        + qr[12]*k3.x + qr[13]*k3.y + qr[14]*k3.z + qr[15]*k3.w;
                s += __shfl_xor_sync(0xffffffffu, s, 1);
                s += __shfl_xor_sync(0xffffffffu, s, 2);
                s += __shfl_xor_sync(0xffffffffu, s, 4);

                if (s > m) {
                    const float c = __expf(m - s);
                    l *= c;
                    #pragma unroll
                    for (int k = 0; k < 16; k++) acc[k] *= c;
                    m = s;
                }
                const float p = __expf(s - m);
                l += p;
                acc[0]  += p * v0.x;  acc[1]  += p * v0.y;  acc[2]  += p * v0.z;  acc[3]  += p * v0.w;
                acc[4]  += p * v1.x;  acc[5]  += p * v1.y;  acc[6]  += p * v1.z;  acc[7]  += p * v1.w;
                acc[8]  += p * v2.x;  acc[9]  += p * v2.y;  acc[10] += p * v2.z;  acc[11] += p * v2.w;
                acc[12] += p * v3.x;  acc[13] += p * v3.y;  acc[14] += p * v3.z;  acc[15] += p * v3.w;
            }
        }
        __syncthreads();

        const int nx = st + DEPTH;
        if (nx < STAGES_TOT) {
            const int blk = __ldg(btb + nx);
            const size_t o = (size_t)blk * 16384 + (size_t)kh * 2048;
            issue_stage(stb, Kc + o, Vc + o, tid);     // same slot just consumed
        }
        cp_commit();   // always commit (possibly empty group) to keep wait_group counting sound
    }

    // CTA-level combine of the 8 warp partials (aliased into the ring smem)
    float* s_acc = (float*)ssm;                 // [WARPS][G_][D_] = 4096 floats
    float* s_m   = (float*)ssm + 4096;          // [WARPS][G_]
    float* s_l   = (float*)ssm + 4096 + 32;     // [WARPS][G_]

    #pragma unroll
    for (int k = 0; k < 16; k++) s_acc[(w * G_ + g) * D_ + d0 + k] = acc[k];
    if (seg == 0) { s_m[w * G_ + g] = m; s_l[w * G_ + g] = l; }
    __syncthreads();

    for (int idx = tid; idx < G_ * D_; idx += 256) {
        const int gg = idx >> 7;
        const int d  = idx & 127;
        float M = -1e30f;
        #pragma unroll
        for (int ww = 0; ww < WARPS; ww++) M = fmaxf(M, s_m[ww * G_ + gg]);
        float A = 0.f, L = 0.f;
        #pragma unroll
        for (int ww = 0; ww < WARPS; ww++) {
            const float c = __expf(s_m[ww * G_ + gg] - M);
            A += s_acc[(ww * G_ + gg) * D_ + d] * c;
            L += s_l[ww * G_ + gg] * c;
        }
        const size_t o = (((size_t)b * HKV_ + kh) * SPLIT + sp) * G_ + gg;
        g_pacc[o * D_ + d] = A;
        if (d == 0) { g_pml[o * 2] = M; g_pml[o * 2 + 1] = L; }
    }
}

__global__ __launch_bounds__(128)
void attn_combine(const float* __restrict__ Q,
                  const float* __restrict__ K,
                  const float* __restrict__ V,
                  const float* __restrict__ cosp,
                  const float* __restrict__ sinp,
                  float* __restrict__ out)
{
    const int h = blockIdx.x;
    const int b = blockIdx.y;
    const int g  = h >> 3;
    const int kh = h & 7;
    const int d    = threadIdx.x;     // 0..127
    const int lane = d & 31;
    const int wrp  = d >> 5;

    const float cv = cosp[(size_t)b * D_ + d];
    const float sv = sinp[(size_t)b * D_ + d];
    const float sign = (d < 64) ? -1.f : 1.f;
    const float* qb = Q + ((size_t)b * H_ + h) * D_;
    const float* kb = K + ((size_t)b * HKV_ + kh) * D_;
    const float qrv = qb[d] * cv + sign * qb[d ^ 64] * sv;
    const float krv = kb[d] * cv + sign * kb[d ^ 64] * sv;

    __shared__ float red[4];
    float part = qrv * krv;
    #pragma unroll
    for (int o = 16; o; o >>= 1) part += __shfl_xor_sync(0xffffffffu, part, o);
    if (lane == 0) red[wrp] = part;
    __syncthreads();
    const float s_cur = (red[0] + red[1] + red[2] + red[3]) * SCALE_;

    const size_t base = ((size_t)b * HKV_ + kh) * SPLIT * G_ + g;
    float M = s_cur;
    #pragma unroll
    for (int i = 0; i < SPLIT; i++)
        M = fmaxf(M, g_pml[(base + (size_t)i * G_) * 2]);

    float ec = __expf(s_cur - M);
    float L  = ec;
    float o_ = ec * V[((size_t)b * HKV_ + kh) * D_ + d];   // current token: raw V
    #pragma unroll
    for (int i = 0; i < SPLIT; i++) {
        const size_t pi = base + (size_t)i * G_;
        const float c = __expf(g_pml[pi * 2] - M);
        L  += g_pml[pi * 2 + 1] * c;
        o_ += g_pacc[pi * D_ + d] * c;
    }
    out[((size_t)b * H_ + h) * D_ + d] = o_ / L;
}

extern "C" void kernel_launch(void* const* d_in, const int* in_sizes, int n_in,
                              void* d_out, int out_size)
{
    const float* Q    = (const float*)d_in[0];
    const float* K    = (const float*)d_in[1];
    const float* V    = (const float*)d_in[2];
    const float* Kc   = (const float*)d_in[3];
    const float* Vc   = (const float*)d_in[4];
    const float* cosp = (const float*)d_in[5];
    const float* sinp = (const float*)d_in[6];
    const int*   bt   = (const int*)d_in[7];
    float* out = (float*)d_out;

    dim3 grid_main(SPLIT, HKV_, B_);
    attn_main<<<grid_main, 256>>>(Q, Kc, Vc, cosp, sinp, bt);

    dim3 grid_comb(H_, B_);
    attn_combine<<<grid_comb, 128>>>(Q, K, V, cosp, sinp, out);
}

// round 4
// speedup vs baseline: 3.2149x; 3.2149x over previous
#include <cuda_runtime.h>
#include <cstdint>
#include <math.h>

#define DEV_INLINE __device__ __forceinline__

constexpr int B_   = 32;
constexpr int H_   = 32;
constexpr int HKV_ = 8;
constexpr int D_   = 128;
constexpr int G_   = 4;      // H_/HKV_
constexpr int N_   = 4096;
constexpr int NB_  = 256;    // 16-token paged blocks per sequence
constexpr int SPLIT = 8;     // token splits per (b,kh)
constexpr int WARPS = 8;
constexpr int TPS = N_ / SPLIT;     // 512 tokens per CTA
constexpr int TPW = TPS / WARPS;    // 64 tokens per warp
constexpr int NSTG = TPW / 2;       // 32 warp-stages of 2 tokens
constexpr int DEPTH = 3;            // warp-private ring slots
constexpr int SLOT_F = 512;         // floats per slot: 2 tok x (128 K + 128 V)
constexpr float SCALE_ = 0.08838834764831845f;

// Partial scratch (allocation-free __device__ globals)
// layout: [b][kh][split][g] -> acc[128], (M,L)
__device__ float g_pacc[(size_t)B_ * HKV_ * SPLIT * G_ * D_];
__device__ float g_pml[(size_t)B_ * HKV_ * SPLIT * G_ * 2];

DEV_INLINE void cp_async16(unsigned int smem_addr, const void* gptr) {
    asm volatile("cp.async.cg.shared.global [%0], [%1], 16;\n"
                 :: "r"(smem_addr), "l"(gptr));
}
DEV_INLINE void cp_commit() { asm volatile("cp.async.commit_group;\n"); }
template <int NN> DEV_INLINE void cp_wait() {
    asm volatile("cp.async.wait_group %0;\n" :: "n"(NN));
}

__global__ void noop_kernel() {}

__global__ __launch_bounds__(256, 3)
void attn_main(const float* __restrict__ Q,
               const float* __restrict__ Kc,
               const float* __restrict__ Vc,
               const float* __restrict__ cosp,
               const float* __restrict__ sinp,
               const int* __restrict__ bt)
{
    const int b  = blockIdx.z;
    const int kh = blockIdx.y;
    const int sp = blockIdx.x;
    const int tid = threadIdx.x;
    const int w   = tid >> 5;
    const int lid = tid & 31;
    const int g   = lid >> 3;        // query-head group 0..3
    const int seg = lid & 7;         // d-chunk owner 0..7
    const int h   = g * HKV_ + kh;

    // 48 KB static: 8 warp-private rings of DEPTH x SLOT_F floats
    __shared__ __align__(16) float ssm[WARPS * DEPTH * SLOT_F];
    float* ring = ssm + w * (DEPTH * SLOT_F);

    // Lane owns d = i*32 + seg*4 + j  (i=0..3, j=0..3) -> conflict-free LDS.128
    // RoPE'd + pre-scaled Q for owned elements
    float qr[16];
    {
        const float* qb = Q + ((size_t)b * H_ + h) * D_;
        const float* cb = cosp + (size_t)b * D_;
        const float* sb = sinp + (size_t)b * D_;
        #pragma unroll
        for (int i = 0; i < 4; i++) {
            #pragma unroll
            for (int j = 0; j < 4; j++) {
                const int d = i * 32 + seg * 4 + j;
                const float sign = (d < 64) ? -1.f : 1.f;
                qr[i * 4 + j] = (qb[d] * cb[d] + sign * qb[d ^ 64] * sb[d]) * SCALE_;
            }
        }
    }

    // 4 paged blocks per warp; precompute flat offsets
    const int* btb = bt + (size_t)b * NB_ + sp * (TPS / 16) + w * (TPW / 16);
    size_t boff[4];
    #pragma unroll
    for (int i = 0; i < 4; i++)
        boff[i] = (size_t)__ldg(btb + i) * 16384 + (size_t)kh * 2048;

    // issue one 2-token stage into this warp's ring (slot layout:
    // [tok0 K 512B | tok0 V 512B | tok1 K | tok1 V])
    auto issue = [&](int st) {
        const size_t o = boff[st >> 3] + (size_t)((st * 2) & 15) * 128;
        const float* gK = Kc + o;
        const float* gV = Vc + o;
        unsigned int s = (unsigned int)__cvta_generic_to_shared(ring + (st % DEPTH) * SLOT_F);
        cp_async16(s +    0 + lid * 16, gK + lid * 4);
        cp_async16(s +  512 + lid * 16, gV + lid * 4);
        cp_async16(s + 1024 + lid * 16, gK + 128 + lid * 4);
        cp_async16(s + 1536 + lid * 16, gV + 128 + lid * 4);
    };

    issue(0); cp_commit();
    issue(1); cp_commit();

    float m = -1e30f, l = 0.f;
    float acc[16];
    #pragma unroll
    for (int k = 0; k < 16; k++) acc[k] = 0.f;

    const int tg0 = sp * TPS + w * TPW;

    for (int st = 0; st < NSTG; st++) {
        cp_wait<1>();                       // stage st arrived (own warp's group)
        const float* slot = ring + (st % DEPTH) * SLOT_F;
        const int njj = min(2, (N_ - 1) - (tg0 + st * 2));  // exclude current token

        #pragma unroll
        for (int jj = 0; jj < 2; jj++) {
            if (jj < njj) {
                const float4* kK = reinterpret_cast<const float4*>(slot + jj * 256);
                const float4* kV = kK + 32;
                float4 k0 = kK[seg], k1 = kK[8 + seg], k2 = kK[16 + seg], k3 = kK[24 + seg];
                float4 v0 = kV[seg], v1 = kV[8 + seg], v2 = kV[16 + seg], v3 = kV[24 + seg];

                float s = qr[0]*k0.x + qr[1]*k0.y + qr[2]*k0.z + qr[3]*k0.w
                        + qr[4]*k1.x + qr[5]*k1.y + qr[6]*k1.z + qr[7]*k1.w
                        + qr[8]*k2.x + qr[9]*k2.y + qr[10]*k2.z + qr[11]*k2.w
                        + qr[12]*k3.x + qr[13]*k3.y + qr[14]*k3.z + qr[15]*k3.w;
                s += __shfl_xor_sync(0xffffffffu, s, 1);
                s += __shfl_xor_sync(0xffffffffu, s, 2);
                s += __shfl_xor_sync(0xffffffffu, s, 4);

                if (s > m) {
                    const float c = __expf(m - s);
                    l *= c;
                    #pragma unroll
                    for (int k = 0; k < 16; k++) acc[k] *= c;
                    m = s;
                }
                const float p = __expf(s - m);
                l += p;
                acc[0]  += p * v0.x;  acc[1]  += p * v0.y;  acc[2]  += p * v0.z;  acc[3]  += p * v0.w;
                acc[4]  += p * v1.x;  acc[5]  += p * v1.y;  acc[6]  += p * v1.z;  acc[7]  += p * v1.w;
                acc[8]  += p * v2.x;  acc[9]  += p * v2.y;  acc[10] += p * v2.z;  acc[11] += p * v2.w;
                acc[12] += p * v3.x;  acc[13] += p * v3.y;  acc[14] += p * v3.z;  acc[15] += p * v3.w;
            }
        }

        if (st + 2 < NSTG) issue(st + 2);   // refill slot just consumed (own warp -> no barrier)
        cp_commit();                        // possibly-empty group keeps wait counting sound
    }

    cp_wait<0>();
    __syncthreads();

    // CTA-level combine of 8 warp partials (aliased into ring smem)
    float* s_acc = ssm;                 // [WARPS][G_][D_] = 4096 floats
    float* s_m   = ssm + 4096;          // [WARPS][G_]
    float* s_l   = ssm + 4096 + 32;

    #pragma unroll
    for (int i = 0; i < 4; i++)
        #pragma unroll
        for (int j = 0; j < 4; j++)
            s_acc[(w * G_ + g) * D_ + i * 32 + seg * 4 + j] = acc[i * 4 + j];
    if (seg == 0) { s_m[w * G_ + g] = m; s_l[w * G_ + g] = l; }
    __syncthreads();

    for (int idx = tid; idx < G_ * D_; idx += 256) {
        const int gg = idx >> 7;
        const int d  = idx & 127;
        float M = -1e30f;
        #pragma unroll
        for (int ww = 0; ww < WARPS; ww++) M = fmaxf(M, s_m[ww * G_ + gg]);
        float A = 0.f, L = 0.f;
        #pragma unroll
        for (int ww = 0; ww < WARPS; ww++) {
            const float c = __expf(s_m[ww * G_ + gg] - M);
            A += s_acc[(ww * G_ + gg) * D_ + d] * c;
            L += s_l[ww * G_ + gg] * c;
        }
        const size_t o = (((size_t)b * HKV_ + kh) * SPLIT + sp) * G_ + gg;
        g_pacc[o * D_ + d] = A;
        if (d == 0) { g_pml[o * 2] = M; g_pml[o * 2 + 1] = L; }
    }
}

__global__ __launch_bounds__(128)
void attn_combine(const float* __restrict__ Q,
                  const float* __restrict__ K,
                  const float* __restrict__ V,
                  const float* __restrict__ cosp,
                  const float* __restrict__ sinp,
                  float* __restrict__ out)
{
    const int h = blockIdx.x;
    const int b = blockIdx.y;
    const int g  = h >> 3;
    const int kh = h & 7;
    const int d    = threadIdx.x;     // 0..127
    const int lane = d & 31;
    const int wrp  = d >> 5;

    const float cv = cosp[(size_t)b * D_ + d];
    const float sv = sinp[(size_t)b * D_ + d];
    const float sign = (d < 64) ? -1.f : 1.f;
    const float* qb = Q + ((size_t)b * H_ + h) * D_;
    const float* kb = K + ((size_t)b * HKV_ + kh) * D_;
    const float qrv = qb[d] * cv + sign * qb[d ^ 64] * sv;
    const float krv = kb[d] * cv + sign * kb[d ^ 64] * sv;

    __shared__ float red[4];
    float part = qrv * krv;
    #pragma unroll
    for (int o = 16; o; o >>= 1) part += __shfl_xor_sync(0xffffffffu, part, o);
    if (lane == 0) red[wrp] = part;
    __syncthreads();
    const float s_cur = (red[0] + red[1] + red[2] + red[3]) * SCALE_;

    const size_t base = ((size_t)b * HKV_ + kh) * SPLIT * G_ + g;
    float M = s_cur;
    #pragma unroll
    for (int i = 0; i < SPLIT; i++)
        M = fmaxf(M, g_pml[(base + (size_t)i * G_) * 2]);

    float ec = __expf(s_cur - M);
    float L  = ec;
    float o_ = ec * V[((size_t)b * HKV_ + kh) * D_ + d];   // current token: raw V
    #pragma unroll
    for (int i = 0; i < SPLIT; i++) {
        const size_t pi = base + (size_t)i * G_;
        const float c = __expf(g_pml[pi * 2] - M);
        L  += g_pml[pi * 2 + 1] * c;
        o_ += g_pacc[pi * D_ + d] * c;
    }
    out[((size_t)b * H_ + h) * D_ + d] = o_ / L;
}

extern "C" void kernel_launch(void* const* d_in, const int* in_sizes, int n_in,
                              void* d_out, int out_size)
{
    const float* Q    = (const float*)d_in[0];
    const float* K    = (const float*)d_in[1];
    const float* V    = (const float*)d_in[2];
    const float* Kc   = (const float*)d_in[3];
    const float* Vc   = (const float*)d_in[4];
    const float* cosp = (const float*)d_in[5];
    const float* sinp = (const float*)d_in[6];
    const int*   bt   = (const int*)d_in[7];
    float* out = (float*)d_out;

    // 4 launches/call so ncu (-s 5 -c 1) lands on attn_main (launch #5)
    noop_kernel<<<1, 32>>>();

    dim3 grid_main(SPLIT, HKV_, B_);
    attn_main<<<grid_main, 256>>>(Q, Kc, Vc, cosp, sinp, bt);

    dim3 grid_comb(H_, B_);
    attn_combine<<<grid_comb, 128>>>(Q, K, V, cosp, sinp, out);

    noop_kernel<<<1, 32>>>();
}